// round 7
// baseline (speedup 1.0000x reference)
#include <cuda_runtime.h>
#include <cstdint>

// Problem constants
constexpr int Bb = 8;
constexpr int Nn = 1024;
constexpr int Cc = 768;
constexpr int Hh = 12;
constexpr int HDd = 64;
constexpr int Vv = 8;

constexpr int M1  = Bb * Nn;       // 8192
constexpr int MKV = Vv * Bb * Nn;  // 65536
constexpr int KVW = 2 * HDd;       // 128

// ---------------------------------------------------------------------------
// Scratch
// ---------------------------------------------------------------------------
__device__ float g_q[M1 * Cc];
__device__ float g_kv[MKV * KVW];
__device__ float g_ao[M1 * Cc];     // tf32-pre-rounded by attn_kernel
__device__ float g_wq[Cc * Cc];     // tf32-rounded weights
__device__ float g_wkv[KVW * Cc];
__device__ float g_wp[Cc * Cc];

__device__ __forceinline__ uint32_t smem_u32(const void* p) {
    uint32_t a;
    asm("{ .reg .u64 t; cvta.to.shared.u64 t, %1; cvt.u32.u64 %0, t; }"
        : "=r"(a) : "l"(p));
    return a;
}

__device__ __forceinline__ unsigned f2tf32(float f) {
    unsigned r;
    asm volatile("cvt.rna.tf32.f32 %0, %1;" : "=r"(r) : "f"(f));
    return r;
}

#define CP_ASYNC16(dst, src)                                                  \
    asm volatile("cp.async.ca.shared.global [%0], [%1], 16;\n"                \
                 :: "r"(dst), "l"(src))
#define CP_COMMIT() asm volatile("cp.async.commit_group;\n" ::: "memory")
#define CP_WAIT1()  asm volatile("cp.async.wait_group 1;\n" ::: "memory")

#define MMA_TF32(c, a, b)                                                   \
    asm volatile(                                                           \
        "mma.sync.aligned.m16n8k8.row.col.f32.tf32.tf32.f32 "               \
        "{%0,%1,%2,%3}, {%4,%5,%6,%7}, {%8,%9}, {%0,%1,%2,%3};\n"           \
        : "+f"((c)[0]), "+f"((c)[1]), "+f"((c)[2]), "+f"((c)[3])            \
        : "r"((a)[0]), "r"((a)[1]), "r"((a)[2]), "r"((a)[3]),               \
          "r"((b)[0]), "r"((b)[1]))

#define LDSM_X4(r0, r1, r2, r3, addr)                                       \
    asm volatile(                                                           \
        "ldmatrix.sync.aligned.m8n8.x4.shared.b16 {%0,%1,%2,%3}, [%4];"     \
        : "=r"(r0), "=r"(r1), "=r"(r2), "=r"(r3) : "r"(addr))

// ---------------------------------------------------------------------------
// TF32 warp-MMA GEMM-NT: CTA 128x128, 4 warps (2M x 2N grid of 64x64 tiles),
// BK=32 (144B rows), 3-stage cp.async, single barrier per k-tile.
// Re-read amplification: A x2, B x2 (vs x2/x4 before) -> smem-BW relief.
// ---------------------------------------------------------------------------
constexpr int STAGES = 3;
constexpr int BK = 32;
constexpr int ROWPAD = 36;                    // floats per row (144 B)
constexpr int TILE_FLOATS = 128 * ROWPAD;     // per matrix per stage
constexpr int STAGE_BYTES = 2 * TILE_FLOATS * 4;
constexpr int GEMM_SMEM = STAGES * STAGE_BYTES;  // 110592
constexpr int MT_STRIDE = 16 * ROWPAD * 4;       // 2304 bytes / 16 rows

template <bool CVTA>
__device__ __forceinline__
void gemm_body(const float* __restrict__ A,
               const float* __restrict__ W,
               const float* __restrict__ bias,
               float* __restrict__ C,
               int N, int K, int bm, int bn,
               uint32_t sb)
{
    const int t    = threadIdx.x;       // 0..127
    const int wid  = t >> 5;            // 0..3
    const int lane = t & 31;
    const int lq   = lane >> 2;
    const int lr   = lane & 3;

    const int warp_m = (wid & 1) * 64;
    const int warp_n = (wid >> 1) * 64;

    // cp.async: 1024 16B chunks per matrix per k-tile; 8 per thread.
    // chunk f: row = f>>3, c = f&7 (k float offset c*4)
    size_t offA[8], offB[8];
    uint32_t dA[8], dB[8];
    #pragma unroll
    for (int i = 0; i < 8; i++) {
        const int f = t + 128 * i;
        const int r = f >> 3, c = f & 7;
        offA[i] = (size_t)(bm + r) * K + c * 4;
        offB[i] = (size_t)(bn + r) * K + c * 4;
        dA[i]   = (uint32_t)(r * ROWPAD + c * 4) * 4;
        dB[i]   = dA[i] + TILE_FLOATS * 4;
    }

    auto issue_tile = [&](int kt) {
        const uint32_t base = sb + (uint32_t)(kt % STAGES) * STAGE_BYTES;
        const size_t ko = (size_t)kt * BK;
        #pragma unroll
        for (int i = 0; i < 8; i++) {
            CP_ASYNC16(base + dA[i], A + offA[i] + ko);
            CP_ASYNC16(base + dB[i], W + offB[i] + ko);
        }
    };

    // ldmatrix per-lane offsets (bytes within stage)
    const uint32_t aOff =
        (uint32_t)((warp_m + ((lane >> 3) & 1) * 8 + (lane & 7)) * ROWPAD
                   + (lane >> 4) * 4) * 4;
    const uint32_t bOff =
        (uint32_t)((warp_n + (lane >> 4) * 8 + (lane & 7)) * ROWPAD
                   + ((lane >> 3) & 1) * 4) * 4
        + TILE_FLOATS * 4;

    float acc[4][8][4];
    #pragma unroll
    for (int mt = 0; mt < 4; mt++)
        #pragma unroll
        for (int nt = 0; nt < 8; nt++)
            #pragma unroll
            for (int i = 0; i < 4; i++)
                acc[mt][nt][i] = 0.0f;

    const int NT = K / BK;              // 24

    issue_tile(0); CP_COMMIT();
    issue_tile(1); CP_COMMIT();

    unsigned afr[2][4][4];
    unsigned bfr[2][8][2];

    auto load_half = [&](int buf, uint32_t stBase, int kk) {
        const uint32_t kOfs = kk * 4;
        #pragma unroll
        for (int mt = 0; mt < 4; mt++)
            LDSM_X4(afr[buf][mt][0], afr[buf][mt][1],
                    afr[buf][mt][2], afr[buf][mt][3],
                    stBase + aOff + mt * MT_STRIDE + kOfs);
        #pragma unroll
        for (int p = 0; p < 4; p++)
            LDSM_X4(bfr[buf][2 * p][0], bfr[buf][2 * p][1],
                    bfr[buf][2 * p + 1][0], bfr[buf][2 * p + 1][1],
                    stBase + bOff + p * MT_STRIDE + kOfs);
    };

    auto compute_half = [&](int buf) {
        if (CVTA) {
            #pragma unroll
            for (int mt = 0; mt < 4; mt++)
                #pragma unroll
                for (int i = 0; i < 4; i++)
                    afr[buf][mt][i] =
                        f2tf32(__uint_as_float(afr[buf][mt][i]));
        }
        #pragma unroll
        for (int mt = 0; mt < 4; mt++)
            #pragma unroll
            for (int nt = 0; nt < 8; nt++)
                MMA_TF32(acc[mt][nt], afr[buf][mt], bfr[buf][nt]);
    };

    for (int kt = 0; kt < NT; kt++) {
        CP_WAIT1();
        __syncthreads();

        if (kt + 2 < NT) issue_tile(kt + 2);
        CP_COMMIT();

        const uint32_t stBase = sb + (uint32_t)(kt % STAGES) * STAGE_BYTES;

        load_half(0, stBase, 0);
        #pragma unroll
        for (int h = 0; h < 4; h++) {
            if (h < 3) load_half((h + 1) & 1, stBase, (h + 1) * 8);
            compute_half(h & 1);
        }
    }

    // epilogue
    #pragma unroll
    for (int mt = 0; mt < 4; mt++) {
        const int row0 = bm + warp_m + mt * 16 + lq;
        #pragma unroll
        for (int nt = 0; nt < 8; nt++) {
            const int col = bn + warp_n + nt * 8 + 2 * lr;
            float b0 = 0.f, b1 = 0.f;
            if (bias) { b0 = bias[col]; b1 = bias[col + 1]; }
            float2 v01 = make_float2(acc[mt][nt][0] + b0, acc[mt][nt][1] + b1);
            float2 v23 = make_float2(acc[mt][nt][2] + b0, acc[mt][nt][3] + b1);
            *reinterpret_cast<float2*>(C + (size_t)row0 * N + col) = v01;
            *reinterpret_cast<float2*>(C + (size_t)(row0 + 8) * N + col) = v23;
        }
    }
}

// Merged q-GEMM + kv-GEMM
constexpr int QK_GRID_Q = (Cc / 128) * (M1 / 128);    // 384
constexpr int QK_GRID   = QK_GRID_Q + (MKV / 128);    // 896

__global__ __launch_bounds__(128, 2)
void qkv_gemm(const float* __restrict__ x,  const float* __restrict__ wq,
              const float* __restrict__ vp, const float* __restrict__ wkv,
              float* __restrict__ q, float* __restrict__ kv)
{
    extern __shared__ float sm[];
    const uint32_t sb = smem_u32(sm);
    const int bid = blockIdx.x;
    if (bid < QK_GRID_Q) {
        const int bx = bid % (Cc / 128);
        const int by = bid / (Cc / 128);
        gemm_body<true>(x, wq, nullptr, q, Cc, Cc, by * 128, bx * 128, sb);
    } else {
        const int by = bid - QK_GRID_Q;
        gemm_body<true>(vp, wkv, nullptr, kv, KVW, Cc, by * 128, 0, sb);
    }
}

__global__ __launch_bounds__(128, 2)
void proj_gemm(const float* __restrict__ ao, const float* __restrict__ wp,
               const float* __restrict__ bias, float* __restrict__ out)
{
    extern __shared__ float sm[];
    const uint32_t sb = smem_u32(sm);
    const int bx = blockIdx.x % (Cc / 128);
    const int by = blockIdx.x / (Cc / 128);
    // ao is tf32-pre-rounded by attn_kernel -> no A-side cvt
    gemm_body<false>(ao, wp, bias, out, Cc, Cc, by * 128, bx * 128, sb);
}

// ---------------------------------------------------------------------------
// Weight pre-conversion (one launch)
// ---------------------------------------------------------------------------
constexpr int NW1 = Cc * Cc;
constexpr int NW2 = KVW * Cc;
constexpr int NW_TOT = NW1 + NW2 + NW1;

__global__ void cvt_w_kernel(const float* __restrict__ wq_in,
                             const float* __restrict__ wkv_in,
                             const float* __restrict__ wp_in,
                             float* __restrict__ wq_o,
                             float* __restrict__ wkv_o,
                             float* __restrict__ wp_o)
{
    const int i = blockIdx.x * 256 + threadIdx.x;
    if (i < NW1) {
        wq_o[i] = __uint_as_float(f2tf32(wq_in[i]));
    } else if (i < NW1 + NW2) {
        const int j = i - NW1;
        wkv_o[j] = __uint_as_float(f2tf32(wkv_in[j]));
    } else if (i < NW_TOT) {
        const int j = i - NW1 - NW2;
        wp_o[j] = __uint_as_float(f2tf32(wp_in[j]));
    }
}

// ---------------------------------------------------------------------------
// Fused attention: one CTA per (b,n). Output pre-rounded to tf32.
// ---------------------------------------------------------------------------
__global__ __launch_bounds__(256)
void attn_kernel(const float* __restrict__ q,
                 const float* __restrict__ kvr,
                 float* __restrict__ out)
{
    const int bn = blockIdx.x;
    const int t  = threadIdx.x;

    __shared__ float sq[Cc];
    __shared__ float skv[Vv][KVW];
    __shared__ float slog[Hh * Vv];
    __shared__ float sp[Hh][Vv];

    {
        const float4* src = reinterpret_cast<const float4*>(q + (size_t)bn * Cc);
        float4* dst = reinterpret_cast<float4*>(sq);
        for (int i = t; i < Cc / 4; i += 256) dst[i] = src[i];
    }
    {
        for (int i = t; i < Vv * KVW / 4; i += 256) {
            int v = i / (KVW / 4);
            int d4 = i % (KVW / 4);
            const float4* src = reinterpret_cast<const float4*>(
                kvr + ((size_t)v * (Bb * Nn) + bn) * KVW);
            reinterpret_cast<float4*>(skv[v])[d4] = src[d4];
        }
    }
    __syncthreads();

    #pragma unroll
    for (int rep = 0; rep < 3; rep++) {
        const int task = t + rep * 256;
        const int pair = task >> 3;
        const int sub  = task & 7;
        const int h = pair / Vv;
        const int v = pair % Vv;
        float a = 0.f;
        #pragma unroll
        for (int j = 0; j < 8; j++)
            a = fmaf(sq[h * HDd + sub * 8 + j], skv[v][sub * 8 + j], a);
        a += __shfl_down_sync(0xffffffffu, a, 4);
        a += __shfl_down_sync(0xffffffffu, a, 2);
        a += __shfl_down_sync(0xffffffffu, a, 1);
        if (sub == 0) slog[pair] = a * 0.125f;
    }
    __syncthreads();

    if (t < Hh) {
        float mx = -1e30f;
        #pragma unroll
        for (int v = 0; v < Vv; v++) mx = fmaxf(mx, slog[t * Vv + v]);
        float e[Vv];
        float s = 0.f;
        #pragma unroll
        for (int v = 0; v < Vv; v++) {
            e[v] = __expf(slog[t * Vv + v] - mx);
            s += e[v];
        }
        const float inv = 1.0f / s;
        #pragma unroll
        for (int v = 0; v < Vv; v++) sp[t][v] = e[v] * inv;
    }
    __syncthreads();

    #pragma unroll
    for (int rep = 0; rep < 3; rep++) {
        const int i = t + rep * 256;
        const int h = i / HDd;
        const int d = i % HDd;
        float a = 0.f;
        #pragma unroll
        for (int v = 0; v < Vv; v++)
            a = fmaf(sp[h][v], skv[v][HDd + d], a);
        // pre-round to tf32 so proj_gemm needs no A-side cvt
        out[(size_t)bn * Cc + i] = __uint_as_float(f2tf32(a));
    }
}

// ---------------------------------------------------------------------------
// Launch
// ---------------------------------------------------------------------------
extern "C" void kernel_launch(void* const* d_in, const int* in_sizes, int n_in,
                              void* d_out, int out_size)
{
    const float* x   = (const float*)d_in[0];
    const float* vp  = (const float*)d_in[1];
    const float* Wq  = (const float*)d_in[2];
    const float* Wkv = (const float*)d_in[3];
    const float* Wp  = (const float*)d_in[4];
    const float* bp  = (const float*)d_in[5];
    float* out = (float*)d_out;

    float *q, *kv, *ao, *wq, *wkv, *wp;
    cudaGetSymbolAddress((void**)&q,   g_q);
    cudaGetSymbolAddress((void**)&kv,  g_kv);
    cudaGetSymbolAddress((void**)&ao,  g_ao);
    cudaGetSymbolAddress((void**)&wq,  g_wq);
    cudaGetSymbolAddress((void**)&wkv, g_wkv);
    cudaGetSymbolAddress((void**)&wp,  g_wp);

    cudaFuncSetAttribute(qkv_gemm,
                         cudaFuncAttributeMaxDynamicSharedMemorySize,
                         GEMM_SMEM);
    cudaFuncSetAttribute(proj_gemm,
                         cudaFuncAttributeMaxDynamicSharedMemorySize,
                         GEMM_SMEM);

    // 0) pre-round all weights to tf32
    cvt_w_kernel<<<(NW_TOT + 255) / 256, 256>>>(Wq, Wkv, Wp, wq, wkv, wp);

    // 1+2) q = x @ wq^T  and  kv = vp @ wkv^T  (merged grid)
    qkv_gemm<<<QK_GRID, 128, GEMM_SMEM>>>(x, wq, vp, wkv, q, kv);

    // 3) fused attention per (b,n)  (emits tf32-rounded ao)
    attn_kernel<<<M1, 256>>>(q, kv, ao);

    // 4) out = ao @ wp^T + bproj
    proj_gemm<<<(Cc / 128) * (M1 / 128), 128, GEMM_SMEM>>>(ao, wp, bp, out);
}